// round 2
// baseline (speedup 1.0000x reference)
#include <cuda_runtime.h>
#include <cstdint>

#define NPTS   200000
#define CIN    64
#define COUT   16
#define SXD    998
#define SYD    998
#define SZD    38
#define YZ     37924          /* SYD*SZD */
#define SENTV  37848152u      /* SXD*SYD*SZD */
#define NKTOT  5400000        /* NPTS*27 */
#define WORDS  1182755        /* ceil(SENTV/32) */
#define CHUNK  4096
#define NPART  289            /* ceil(WORDS/CHUNK) */
#define WPAD   (NPART*CHUNK)  /* 1183744 */
#define ZBLK   (WPAD/1024)    /* 1156 zero blocks, 1024 words each */
#define FOB    2048           /* fill blocks in combo kernel */

// ---------------- device scratch (static: allowed) ----------------
__device__ __align__(16) unsigned g_bitmap[WPAD];
__device__ __align__(16) unsigned g_pref[WPAD];
__device__ __align__(16) float    g_Wt[27 * 16 * 64];   /* W transposed [k][o][c] */
__device__ unsigned g_part[NPART];
__device__ unsigned g_M;

#define FMA2(acc, w, f) asm("fma.rn.f32x2 %0, %1, %2, %0;" : "+l"(acc) : "l"(w), "l"(f))

__device__ __forceinline__ float red2(unsigned long long a) {
    float lo, hi;
    asm("mov.b64 {%0,%1}, %2;" : "=f"(lo), "=f"(hi) : "l"(a));
    return lo + hi;
}

// ---------------- kernels ----------------
// zero bitmap + transpose W into [k][o][c]
__global__ void k_zero(const float* __restrict__ W) {
    if (blockIdx.x < ZBLK) {
        unsigned i = blockIdx.x * 1024 + threadIdx.x * 4;
        *reinterpret_cast<uint4*>(&g_bitmap[i]) = make_uint4(0u, 0u, 0u, 0u);
    } else {
        int k = blockIdx.x - ZBLK;
#pragma unroll
        for (int j = 0; j < 4; j++) {
            int idx = threadIdx.x + j * 256;          // 0..1023
            int o = idx >> 6, c = idx & 63;
            g_Wt[k * 1024 + o * 64 + c] = W[k * 1024 + c * 16 + o];
        }
    }
}

__global__ void k_mark(const int4* __restrict__ coords) {
    int n = blockIdx.x * blockDim.x + threadIdx.x;
    if (n >= NPTS) return;
    int4 c = coords[n];
    int x = c.y, y = c.z, z = c.w;
#pragma unroll
    for (int k = 0; k < 27; k++) {
        int ox = x - k / 9;
        int oy = y - (k / 3) % 3;
        int oz = z - k % 3;
        if ((unsigned)ox < SXD && (unsigned)oy < SYD && (unsigned)oz < SZD) {
            unsigned lin = (unsigned)ox * YZ + (unsigned)oy * SZD + (unsigned)oz;
            atomicOr(&g_bitmap[lin >> 5], 1u << (lin & 31));
        }
    }
}

// per-chunk popcount sums
__global__ void k_scan1() {
    __shared__ unsigned sh[256];
    unsigned base = blockIdx.x * CHUNK + threadIdx.x * 16;
    unsigned s = 0;
#pragma unroll
    for (int i = 0; i < 16; i += 4) {
        uint4 v = *reinterpret_cast<const uint4*>(&g_bitmap[base + i]);
        s += __popc(v.x) + __popc(v.y) + __popc(v.z) + __popc(v.w);
    }
    sh[threadIdx.x] = s;
    __syncthreads();
    for (int off = 128; off > 0; off >>= 1) {
        if (threadIdx.x < (unsigned)off) sh[threadIdx.x] += sh[threadIdx.x + off];
        __syncthreads();
    }
    if (threadIdx.x == 0) g_part[blockIdx.x] = sh[0];
}

// exclusive scan of partials (single block), total -> g_M
__global__ void k_scan2() {
    __shared__ unsigned sh[512];
    unsigned t = threadIdx.x;
    unsigned v = (t < NPART) ? g_part[t] : 0u;
    sh[t] = v;
    __syncthreads();
    for (int off = 1; off < 512; off <<= 1) {
        unsigned add = (t >= (unsigned)off) ? sh[t - off] : 0u;
        __syncthreads();
        sh[t] += add;
        __syncthreads();
    }
    if (t < NPART) g_part[t] = sh[t] - v;
    if (t == NPART - 1) g_M = sh[t];
}

// combo: blocks [0,NPART) do the per-word prefix; remaining blocks init out + pad uniq
__global__ void k_combo(float4* __restrict__ out4, const float4* __restrict__ bias4,
                        float* __restrict__ uniqf) {
    if (blockIdx.x < NPART) {
        __shared__ unsigned sh[256];
        unsigned base = blockIdx.x * CHUNK + threadIdx.x * 16;
        unsigned w[16];
#pragma unroll
        for (int i = 0; i < 16; i += 4)
            *reinterpret_cast<uint4*>(&w[i]) = *reinterpret_cast<const uint4*>(&g_bitmap[base + i]);
        unsigned s = 0;
#pragma unroll
        for (int i = 0; i < 16; i++) s += __popc(w[i]);
        sh[threadIdx.x] = s;
        __syncthreads();
        for (int off = 1; off < 256; off <<= 1) {
            unsigned add = (threadIdx.x >= (unsigned)off) ? sh[threadIdx.x - off] : 0u;
            __syncthreads();
            sh[threadIdx.x] += add;
            __syncthreads();
        }
        unsigned run = g_part[blockIdx.x] + (sh[threadIdx.x] - s);
#pragma unroll
        for (int i = 0; i < 16; i++) {
            g_pref[base + i] = run;
            run += __popc(w[i]);
        }
    } else {
        unsigned b = blockIdx.x - NPART;
        unsigned stride = (gridDim.x - NPART) * 256u;
        unsigned M = g_M;
        float4 bsv[4];
#pragma unroll
        for (int j = 0; j < 4; j++) bsv[j] = __ldg(&bias4[j]);
        const float4 z4 = make_float4(0.f, 0.f, 0.f, 0.f);
        for (unsigned i = b * 256u + threadIdx.x; i < (unsigned)NKTOT * 4u; i += stride) {
            unsigned j = i >> 2;
            out4[i] = (j < M) ? bsv[i & 3u] : z4;
        }
        for (unsigned j = b * 256u + threadIdx.x; j < (unsigned)NKTOT; j += stride)
            if (j >= M) uniqf[j] = 37848152.0f;
    }
}

// main compute+scatter: warp = 8 points x 4 output-quads, f32x2 packed FMA
__global__ void __launch_bounds__(256) k_scatter(
    const float* __restrict__ feats, const int4* __restrict__ coords,
    float* __restrict__ out)
{
    int gtid = blockIdx.x * blockDim.x + threadIdx.x;
    int warp = gtid >> 5;
    int lane = threadIdx.x & 31;
    int p = lane >> 2;          // 0..7: point within warp
    int g = lane & 3;           // 0..3: output quad (o = 4g..4g+3)
    int n = warp * 8 + p;
    bool pv = (n < NPTS);
    int nn = pv ? n : 0;
    int4 cc = coords[nn];

    // this point's 64 features as 16 x f32x2-pairs (consecutive c pairs)
    ulonglong2 fr[16];
    const ulonglong2* fp = reinterpret_cast<const ulonglong2*>(feats + (size_t)nn * 64);
#pragma unroll
    for (int i = 0; i < 16; i++) fr[i] = __ldg(&fp[i]);

#pragma unroll 1
    for (int k = 0; k < 27; k++) {
        int ox = cc.y - k / 9;
        int oy = cc.z - (k / 3) % 3;
        int oz = cc.w - k % 3;
        bool valid = pv && (unsigned)ox < SXD && (unsigned)oy < SYD && (unsigned)oz < SZD;

        unsigned rank = 0u;
        if (g == 0 && valid) {
            unsigned lin = (unsigned)ox * YZ + (unsigned)oy * SZD + (unsigned)oz;
            unsigned word = lin >> 5;
            rank = __ldg(&g_pref[word]) +
                   __popc(__ldg(&g_bitmap[word]) & ((1u << (lin & 31)) - 1u));
        }
        rank = __shfl_sync(0xffffffffu, rank, lane & ~3);

        // 4 output rows of Wt[k][o][c], o = 4g..4g+3, each 64 floats contiguous
        const ulonglong2* w0 = reinterpret_cast<const ulonglong2*>(g_Wt + k * 1024 + (4 * g) * 64);
        const ulonglong2* w1 = w0 + 16;
        const ulonglong2* w2 = w0 + 32;
        const ulonglong2* w3 = w0 + 48;

        unsigned long long a0 = 0ull, a1 = 0ull, a2 = 0ull, a3 = 0ull;
#pragma unroll
        for (int i = 0; i < 16; i++) {
            ulonglong2 b0 = __ldg(&w0[i]);
            ulonglong2 b1 = __ldg(&w1[i]);
            ulonglong2 b2 = __ldg(&w2[i]);
            ulonglong2 b3 = __ldg(&w3[i]);
            ulonglong2 f  = fr[i];
            FMA2(a0, b0.x, f.x); FMA2(a0, b0.y, f.y);
            FMA2(a1, b1.x, f.x); FMA2(a1, b1.y, f.y);
            FMA2(a2, b2.x, f.x); FMA2(a2, b2.y, f.y);
            FMA2(a3, b3.x, f.x); FMA2(a3, b3.y, f.y);
        }
        if (valid) {
            float s0 = red2(a0), s1 = red2(a1), s2 = red2(a2), s3 = red2(a3);
            float* dst = out + (size_t)rank * 16 + g * 4;
            asm volatile("red.global.add.v4.f32 [%0], {%1,%2,%3,%4};"
                         :: "l"(dst), "f"(s0), "f"(s1), "f"(s2), "f"(s3)
                         : "memory");
        }
    }
}

// write uniq values (sorted) for occupied cells
__global__ void k_emit(float* __restrict__ uniqf) {
    unsigned i = blockIdx.x * blockDim.x + threadIdx.x;
    if (i >= WORDS) return;
    unsigned bits = g_bitmap[i];
    if (!bits) return;
    unsigned r = g_pref[i];
    unsigned vbase = i << 5;
    while (bits) {
        unsigned b = __ffs(bits) - 1u;
        bits &= bits - 1u;
        uniqf[r++] = (float)(vbase + b);
    }
}

// ---------------- launch ----------------
extern "C" void kernel_launch(void* const* d_in, const int* in_sizes, int n_in,
                              void* d_out, int out_size) {
    const float* feats = (const float*)d_in[0];
    const int*   coords = (const int*)d_in[1];
    const float* W = (const float*)d_in[2];
    const float* bias = (const float*)d_in[3];
    float* out = (float*)d_out;
    float* uniqf = out + (size_t)NKTOT * 16;

    k_zero<<<ZBLK + 27, 256>>>(W);
    k_mark<<<(NPTS + 255) / 256, 256>>>((const int4*)coords);
    k_scan1<<<NPART, 256>>>();
    k_scan2<<<1, 512>>>();
    k_combo<<<NPART + FOB, 256>>>((float4*)out, (const float4*)bias, uniqf);

    int warps = (NPTS + 7) / 8;                 // 25000
    int blocks = (warps + 7) / 8;               // 3125 blocks of 8 warps
    k_scatter<<<blocks, 256>>>(feats, (const int4*)coords, out);

    k_emit<<<(WORDS + 255) / 256, 256>>>(uniqf);
}

// round 3
// speedup vs baseline: 2.9085x; 2.9085x over previous
#include <cuda_runtime.h>
#include <cstdint>

#define NPTS   200000
#define CIN    64
#define COUT   16
#define SXD    998
#define SYD    998
#define SZD    38
#define YZ     37924          /* SYD*SZD */
#define SENTV  37848152u      /* SXD*SYD*SZD */
#define NKTOT  5400000        /* NPTS*27 */
#define WORDS  1182755        /* ceil(SENTV/32) */
#define CHUNK  4096
#define NPART  289            /* ceil(WORDS/CHUNK) */
#define WPAD   (NPART*CHUNK)  /* 1183744 */
#define ZBLK   (WPAD/1024)    /* 1156 zero blocks, 1024 words each */
#define FOB    2048           /* fill blocks in combo kernel */

// ---------------- device scratch (static: allowed) ----------------
__device__ __align__(16) unsigned g_bitmap[WPAD];
__device__ __align__(16) unsigned g_pref[WPAD];
// Wt3[k][i][j][g][t] = W[k][c=4i+t][o=4g+j]; lane (g) reads 16B at
// k*1024 + i*64 + j*16 + g*4 floats -> 4 g-lanes contiguous 64B = 1 wavefront
__device__ __align__(16) float    g_Wt[27 * 1024];
__device__ unsigned g_part[NPART];
__device__ unsigned g_M;

#define FMA2(acc, w, f) asm("fma.rn.f32x2 %0, %1, %2, %0;" : "+l"(acc) : "l"(w), "l"(f))

__device__ __forceinline__ float red2(unsigned long long a) {
    float lo, hi;
    asm("mov.b64 {%0,%1}, %2;" : "=f"(lo), "=f"(hi) : "l"(a));
    return lo + hi;
}

// ---------------- kernels ----------------
// zero bitmap + re-tile W into Wt3
__global__ void k_zero(const float* __restrict__ W) {
    if (blockIdx.x < ZBLK) {
        unsigned i = blockIdx.x * 1024 + threadIdx.x * 4;
        *reinterpret_cast<uint4*>(&g_bitmap[i]) = make_uint4(0u, 0u, 0u, 0u);
    } else {
        int k = blockIdx.x - ZBLK;
#pragma unroll
        for (int u = 0; u < 4; u++) {
            int idx = threadIdx.x + u * 256;          // 0..1023
            int i = idx >> 6;
            int r = idx & 63;
            int j = r >> 4;
            int g = (r >> 2) & 3;
            int t = r & 3;
            int c = 4 * i + t;
            int o = 4 * g + j;
            g_Wt[k * 1024 + idx] = W[k * 1024 + c * 16 + o];
        }
    }
}

__global__ void k_mark(const int4* __restrict__ coords) {
    int n = blockIdx.x * blockDim.x + threadIdx.x;
    if (n >= NPTS) return;
    int4 c = coords[n];
    int x = c.y, y = c.z, z = c.w;
#pragma unroll
    for (int k = 0; k < 27; k++) {
        int ox = x - k / 9;
        int oy = y - (k / 3) % 3;
        int oz = z - k % 3;
        if ((unsigned)ox < SXD && (unsigned)oy < SYD && (unsigned)oz < SZD) {
            unsigned lin = (unsigned)ox * YZ + (unsigned)oy * SZD + (unsigned)oz;
            atomicOr(&g_bitmap[lin >> 5], 1u << (lin & 31));
        }
    }
}

// per-chunk popcount sums
__global__ void k_scan1() {
    __shared__ unsigned sh[256];
    unsigned base = blockIdx.x * CHUNK + threadIdx.x * 16;
    unsigned s = 0;
#pragma unroll
    for (int i = 0; i < 16; i += 4) {
        uint4 v = *reinterpret_cast<const uint4*>(&g_bitmap[base + i]);
        s += __popc(v.x) + __popc(v.y) + __popc(v.z) + __popc(v.w);
    }
    sh[threadIdx.x] = s;
    __syncthreads();
    for (int off = 128; off > 0; off >>= 1) {
        if (threadIdx.x < (unsigned)off) sh[threadIdx.x] += sh[threadIdx.x + off];
        __syncthreads();
    }
    if (threadIdx.x == 0) g_part[blockIdx.x] = sh[0];
}

// exclusive scan of partials (single block), total -> g_M
__global__ void k_scan2() {
    __shared__ unsigned sh[512];
    unsigned t = threadIdx.x;
    unsigned v = (t < NPART) ? g_part[t] : 0u;
    sh[t] = v;
    __syncthreads();
    for (int off = 1; off < 512; off <<= 1) {
        unsigned add = (t >= (unsigned)off) ? sh[t - off] : 0u;
        __syncthreads();
        sh[t] += add;
        __syncthreads();
    }
    if (t < NPART) g_part[t] = sh[t] - v;
    if (t == NPART - 1) g_M = sh[t];
}

// combo: blocks [0,NPART) per-word prefix; remaining blocks init out + pad uniq
__global__ void k_combo(float4* __restrict__ out4, const float4* __restrict__ bias4,
                        float* __restrict__ uniqf) {
    if (blockIdx.x < NPART) {
        __shared__ unsigned sh[256];
        unsigned base = blockIdx.x * CHUNK + threadIdx.x * 16;
        unsigned w[16];
#pragma unroll
        for (int i = 0; i < 16; i += 4)
            *reinterpret_cast<uint4*>(&w[i]) = *reinterpret_cast<const uint4*>(&g_bitmap[base + i]);
        unsigned s = 0;
#pragma unroll
        for (int i = 0; i < 16; i++) s += __popc(w[i]);
        sh[threadIdx.x] = s;
        __syncthreads();
        for (int off = 1; off < 256; off <<= 1) {
            unsigned add = (threadIdx.x >= (unsigned)off) ? sh[threadIdx.x - off] : 0u;
            __syncthreads();
            sh[threadIdx.x] += add;
            __syncthreads();
        }
        unsigned run = g_part[blockIdx.x] + (sh[threadIdx.x] - s);
#pragma unroll
        for (int i = 0; i < 16; i++) {
            g_pref[base + i] = run;
            run += __popc(w[i]);
        }
    } else {
        unsigned b = blockIdx.x - NPART;
        unsigned stride = (gridDim.x - NPART) * 256u;
        unsigned M = g_M;
        float4 bsv[4];
#pragma unroll
        for (int j = 0; j < 4; j++) bsv[j] = __ldg(&bias4[j]);
        const float4 z4 = make_float4(0.f, 0.f, 0.f, 0.f);
        for (unsigned i = b * 256u + threadIdx.x; i < (unsigned)NKTOT * 4u; i += stride) {
            unsigned j = i >> 2;
            out4[i] = (j < M) ? bsv[i & 3u] : z4;
        }
        for (unsigned j = b * 256u + threadIdx.x; j < (unsigned)NKTOT; j += stride)
            if (j >= M) uniqf[j] = 37848152.0f;
    }
}

// main compute+scatter: warp = 8 points x 4 output-quads, channel-pair FMA2
__global__ void __launch_bounds__(256) k_scatter(
    const float* __restrict__ feats, const int4* __restrict__ coords,
    float* __restrict__ out)
{
    int gtid = blockIdx.x * blockDim.x + threadIdx.x;
    int warp = gtid >> 5;
    int lane = threadIdx.x & 31;
    int p = lane >> 2;          // 0..7: point within warp
    int g = lane & 3;           // 0..3: output quad (o = 4g..4g+3)
    int n = warp * 8 + p;
    bool pv = (n < NPTS);
    int nn = pv ? n : 0;
    int4 cc = coords[nn];

    // this point's 64 features as 16 x (f32x2, f32x2): channel pairs
    ulonglong2 fr[16];
    const ulonglong2* fp = reinterpret_cast<const ulonglong2*>(feats + (size_t)nn * 64);
#pragma unroll
    for (int i = 0; i < 16; i++) fr[i] = __ldg(&fp[i]);

#pragma unroll 1
    for (int k = 0; k < 27; k++) {
        int ox = cc.y - k / 9;
        int oy = cc.z - (k / 3) % 3;
        int oz = cc.w - k % 3;
        bool valid = pv && (unsigned)ox < SXD && (unsigned)oy < SYD && (unsigned)oz < SZD;

        unsigned rank = 0u;
        if (g == 0 && valid) {
            unsigned lin = (unsigned)ox * YZ + (unsigned)oy * SZD + (unsigned)oz;
            unsigned word = lin >> 5;
            rank = __ldg(&g_pref[word]) +
                   __popc(__ldg(&g_bitmap[word]) & ((1u << (lin & 31)) - 1u));
        }
        rank = __shfl_sync(0xffffffffu, rank, lane & ~3);

        // lane's W chunks: 16B at k*1024 + i*64 + j*16 + g*4 floats
        const ulonglong2* wb = reinterpret_cast<const ulonglong2*>(g_Wt + k * 1024) + g;

        unsigned long long a0 = 0ull, a1 = 0ull, a2 = 0ull, a3 = 0ull;
#pragma unroll
        for (int i = 0; i < 16; i++) {
            ulonglong2 f = fr[i];
            ulonglong2 b0 = __ldg(&wb[i * 16 + 0]);
            ulonglong2 b1 = __ldg(&wb[i * 16 + 4]);
            ulonglong2 b2 = __ldg(&wb[i * 16 + 8]);
            ulonglong2 b3 = __ldg(&wb[i * 16 + 12]);
            FMA2(a0, b0.x, f.x); FMA2(a0, b0.y, f.y);
            FMA2(a1, b1.x, f.x); FMA2(a1, b1.y, f.y);
            FMA2(a2, b2.x, f.x); FMA2(a2, b2.y, f.y);
            FMA2(a3, b3.x, f.x); FMA2(a3, b3.y, f.y);
        }
        if (valid) {
            float s0 = red2(a0), s1 = red2(a1), s2 = red2(a2), s3 = red2(a3);
            float* dst = out + (size_t)rank * 16 + g * 4;
            asm volatile("red.global.add.v4.f32 [%0], {%1,%2,%3,%4};"
                         :: "l"(dst), "f"(s0), "f"(s1), "f"(s2), "f"(s3)
                         : "memory");
        }
    }
}

// write uniq values (sorted) for occupied cells
__global__ void k_emit(float* __restrict__ uniqf) {
    unsigned i = blockIdx.x * blockDim.x + threadIdx.x;
    if (i >= WORDS) return;
    unsigned bits = g_bitmap[i];
    if (!bits) return;
    unsigned r = g_pref[i];
    unsigned vbase = i << 5;
    while (bits) {
        unsigned b = __ffs(bits) - 1u;
        bits &= bits - 1u;
        uniqf[r++] = (float)(vbase + b);
    }
}

// ---------------- launch ----------------
extern "C" void kernel_launch(void* const* d_in, const int* in_sizes, int n_in,
                              void* d_out, int out_size) {
    const float* feats = (const float*)d_in[0];
    const int*   coords = (const int*)d_in[1];
    const float* W = (const float*)d_in[2];
    const float* bias = (const float*)d_in[3];
    float* out = (float*)d_out;
    float* uniqf = out + (size_t)NKTOT * 16;

    k_zero<<<ZBLK + 27, 256>>>(W);
    k_mark<<<(NPTS + 255) / 256, 256>>>((const int4*)coords);
    k_scan1<<<NPART, 256>>>();
    k_scan2<<<1, 512>>>();
    k_combo<<<NPART + FOB, 256>>>((float4*)out, (const float4*)bias, uniqf);

    int warps = (NPTS + 7) / 8;                 // 25000
    int blocks = (warps + 7) / 8;               // 3125 blocks of 8 warps
    k_scatter<<<blocks, 256>>>(feats, (const int4*)coords, out);

    k_emit<<<(WORDS + 255) / 256, 256>>>(uniqf);
}

// round 5
// speedup vs baseline: 6.3991x; 2.2001x over previous
#include <cuda_runtime.h>
#include <cuda_bf16.h>
#include <cstdint>

#define NPTS   200000
#define CIN    64
#define COUT   16
#define SXD    998
#define SYD    998
#define SZD    38
#define YZ     37924          /* SYD*SZD */
#define SENTV  37848152u
#define NKTOT  5400000        /* NPTS*27 */
#define WORDS  1182755
#define CHUNK  4096
#define NPART  289
#define WPAD   (NPART*CHUNK)
#define ZBLK   (WPAD/1024)
#define FOB    2048

#define NOUT   432            /* 27*16 */
#define BSTR   72             /* padded row stride (bf16 elems) = 144B */
#define TILEM  256
#define NCTA   782            /* ceil(200000/256) */

/* smem layout (bytes) */
#define AH_OFF   0            /* 256*144 = 36864 */
#define AL_OFF   36864
#define BH_OFF   73728        /* 432*144 = 62208 */
#define BL_OFF   135936
#define EPI_OFF  198144       /* 8 warps * 2048 */
#define SMEM_SZ  214528

// ---------------- device scratch ----------------
__device__ __align__(16) unsigned g_bitmap[WPAD];
__device__ __align__(16) unsigned g_pref[WPAD];
__device__ __align__(16) unsigned short g_Bh[NOUT * BSTR];
__device__ __align__(16) unsigned short g_Bl[NOUT * BSTR];
__device__ unsigned g_part[NPART];
__device__ unsigned g_M;

static __device__ __forceinline__ uint32_t smem_u32(const void* p) {
    uint32_t a;
    asm("{ .reg .u64 t; cvta.to.shared.u64 t, %1; cvt.u32.u64 %0, t; }" : "=r"(a) : "l"(p));
    return a;
}

#define MMA(C, A, b0v, b1v) \
    asm volatile("mma.sync.aligned.m16n8k16.row.col.f32.bf16.bf16.f32 " \
        "{%0,%1,%2,%3},{%4,%5,%6,%7},{%8,%9},{%0,%1,%2,%3};" \
        : "+f"((C)[0]), "+f"((C)[1]), "+f"((C)[2]), "+f"((C)[3]) \
        : "r"((A)[0]), "r"((A)[1]), "r"((A)[2]), "r"((A)[3]), "r"(b0v), "r"(b1v))

// ---------------- kernels ----------------
// zero bitmap + build padded bf16 hi/lo B [og][c] (og = k*16+o)
__global__ void k_zero(const float* __restrict__ W) {
    if (blockIdx.x < ZBLK) {
        unsigned i = blockIdx.x * 1024 + threadIdx.x * 4;
        *reinterpret_cast<uint4*>(&g_bitmap[i]) = make_uint4(0u, 0u, 0u, 0u);
    } else {
        int k = blockIdx.x - ZBLK;
#pragma unroll
        for (int u = 0; u < 4; u++) {
            int idx = threadIdx.x + u * 256;          // 0..1023
            int o = idx >> 6, c = idx & 63;
            float v = W[k * 1024 + c * 16 + o];
            __nv_bfloat16 h = __float2bfloat16(v);
            __nv_bfloat16 l = __float2bfloat16(v - __bfloat162float(h));
            int og = k * 16 + o;
            g_Bh[og * BSTR + c] = reinterpret_cast<unsigned short&>(h);
            g_Bl[og * BSTR + c] = reinterpret_cast<unsigned short&>(l);
        }
    }
}

__global__ void k_mark(const int4* __restrict__ coords) {
    int n = blockIdx.x * blockDim.x + threadIdx.x;
    if (n >= NPTS) return;
    int4 c = coords[n];
#pragma unroll
    for (int k = 0; k < 27; k++) {
        int ox = c.y - k / 9;
        int oy = c.z - (k / 3) % 3;
        int oz = c.w - k % 3;
        if ((unsigned)ox < SXD && (unsigned)oy < SYD && (unsigned)oz < SZD) {
            unsigned lin = (unsigned)ox * YZ + (unsigned)oy * SZD + (unsigned)oz;
            atomicOr(&g_bitmap[lin >> 5], 1u << (lin & 31));
        }
    }
}

__global__ void k_scan1() {
    __shared__ unsigned sh[256];
    unsigned base = blockIdx.x * CHUNK + threadIdx.x * 16;
    unsigned s = 0;
#pragma unroll
    for (int i = 0; i < 16; i += 4) {
        uint4 v = *reinterpret_cast<const uint4*>(&g_bitmap[base + i]);
        s += __popc(v.x) + __popc(v.y) + __popc(v.z) + __popc(v.w);
    }
    sh[threadIdx.x] = s;
    __syncthreads();
    for (int off = 128; off > 0; off >>= 1) {
        if (threadIdx.x < (unsigned)off) sh[threadIdx.x] += sh[threadIdx.x + off];
        __syncthreads();
    }
    if (threadIdx.x == 0) g_part[blockIdx.x] = sh[0];
}

__global__ void k_scan2() {
    __shared__ unsigned sh[512];
    unsigned t = threadIdx.x;
    unsigned v = (t < NPART) ? g_part[t] : 0u;
    sh[t] = v;
    __syncthreads();
    for (int off = 1; off < 512; off <<= 1) {
        unsigned add = (t >= (unsigned)off) ? sh[t - off] : 0u;
        __syncthreads();
        sh[t] += add;
        __syncthreads();
    }
    if (t < NPART) g_part[t] = sh[t] - v;
    if (t == NPART - 1) g_M = sh[t];
}

__global__ void k_combo(float4* __restrict__ out4, const float4* __restrict__ bias4,
                        float* __restrict__ uniqf) {
    if (blockIdx.x < NPART) {
        __shared__ unsigned sh[256];
        unsigned base = blockIdx.x * CHUNK + threadIdx.x * 16;
        unsigned w[16];
#pragma unroll
        for (int i = 0; i < 16; i += 4)
            *reinterpret_cast<uint4*>(&w[i]) = *reinterpret_cast<const uint4*>(&g_bitmap[base + i]);
        unsigned s = 0;
#pragma unroll
        for (int i = 0; i < 16; i++) s += __popc(w[i]);
        sh[threadIdx.x] = s;
        __syncthreads();
        for (int off = 1; off < 256; off <<= 1) {
            unsigned add = (threadIdx.x >= (unsigned)off) ? sh[threadIdx.x - off] : 0u;
            __syncthreads();
            sh[threadIdx.x] += add;
            __syncthreads();
        }
        unsigned run = g_part[blockIdx.x] + (sh[threadIdx.x] - s);
#pragma unroll
        for (int i = 0; i < 16; i++) {
            g_pref[base + i] = run;
            run += __popc(w[i]);
        }
    } else {
        unsigned b = blockIdx.x - NPART;
        unsigned stride = (gridDim.x - NPART) * 256u;
        unsigned M = g_M;
        float4 bsv[4];
#pragma unroll
        for (int j = 0; j < 4; j++) bsv[j] = __ldg(&bias4[j]);
        const float4 z4 = make_float4(0.f, 0.f, 0.f, 0.f);
        for (unsigned i = b * 256u + threadIdx.x; i < (unsigned)NKTOT * 4u; i += stride) {
            unsigned j = i >> 2;
            out4[i] = (j < M) ? bsv[i & 3u] : z4;
        }
        for (unsigned j = b * 256u + threadIdx.x; j < (unsigned)NKTOT; j += stride)
            if (j >= M) uniqf[j] = 37848152.0f;
    }
}

__global__ void k_emit(float* __restrict__ uniqf) {
    unsigned i = blockIdx.x * blockDim.x + threadIdx.x;
    if (i >= WORDS) return;
    unsigned bits = g_bitmap[i];
    if (!bits) return;
    unsigned r = g_pref[i];
    unsigned vbase = i << 5;
    while (bits) {
        unsigned b = __ffs(bits) - 1u;
        bits &= bits - 1u;
        uniqf[r++] = (float)(vbase + b);
    }
}

// ---------------- HMMA GEMM + fused scatter ----------------
__global__ void __launch_bounds__(256, 1) k_gemm(
    const float4* __restrict__ feats4, const int4* __restrict__ coords,
    float* __restrict__ out)
{
    extern __shared__ char smem[];
    uint32_t sb = smem_u32(smem);
    int tid = threadIdx.x;
    int wid = tid >> 5;
    int lane = tid & 31;
    int base_n = blockIdx.x * TILEM;

    // stage B hi/lo (pre-split, padded) — linear uint4 copies
    {
        const uint4* bh = reinterpret_cast<const uint4*>(g_Bh);
        const uint4* bl = reinterpret_cast<const uint4*>(g_Bl);
        uint4* dh = reinterpret_cast<uint4*>(smem + BH_OFF);
        uint4* dl = reinterpret_cast<uint4*>(smem + BL_OFF);
        for (int i = tid; i < 3888; i += 256) {
            dh[i] = __ldg(&bh[i]);
            dl[i] = __ldg(&bl[i]);
        }
    }
    // stage A tile (256 rows x 64 feats) as bf16 hi/lo, padded stride 144B
    for (int i = tid; i < 4096; i += 256) {            // 256 rows x 16 float4
        int r = i >> 4, col = i & 15;
        int n = base_n + r;
        float4 f = (n < NPTS) ? __ldg(&feats4[(size_t)n * 16 + col])
                              : make_float4(0.f, 0.f, 0.f, 0.f);
        __nv_bfloat16 h0 = __float2bfloat16(f.x), h1 = __float2bfloat16(f.y);
        __nv_bfloat16 h2 = __float2bfloat16(f.z), h3 = __float2bfloat16(f.w);
        __nv_bfloat16 l0 = __float2bfloat16(f.x - __bfloat162float(h0));
        __nv_bfloat16 l1 = __float2bfloat16(f.y - __bfloat162float(h1));
        __nv_bfloat16 l2 = __float2bfloat16(f.z - __bfloat162float(h2));
        __nv_bfloat16 l3 = __float2bfloat16(f.w - __bfloat162float(h3));
        uint2 hv, lv;
        hv.x = (unsigned)reinterpret_cast<unsigned short&>(h0) |
               ((unsigned)reinterpret_cast<unsigned short&>(h1) << 16);
        hv.y = (unsigned)reinterpret_cast<unsigned short&>(h2) |
               ((unsigned)reinterpret_cast<unsigned short&>(h3) << 16);
        lv.x = (unsigned)reinterpret_cast<unsigned short&>(l0) |
               ((unsigned)reinterpret_cast<unsigned short&>(l1) << 16);
        lv.y = (unsigned)reinterpret_cast<unsigned short&>(l2) |
               ((unsigned)reinterpret_cast<unsigned short&>(l3) << 16);
        unsigned off = (unsigned)r * 144u + (unsigned)col * 8u;
        *reinterpret_cast<uint2*>(smem + AH_OFF + off) = hv;
        *reinterpret_cast<uint2*>(smem + AL_OFF + off) = lv;
    }
    __syncthreads();

    // per-warp A fragments (32 rows): ah/al[rg][ks][4]
    int warpRow = wid * 32;
    uint32_t ah[2][4][4], al[2][4][4];
    {
        uint32_t abase = sb + AH_OFF + (unsigned)(warpRow + (lane & 15)) * 144u
                       + ((unsigned)(lane >> 4) & 1u) * 16u;
#pragma unroll
        for (int rg = 0; rg < 2; rg++) {
#pragma unroll
            for (int ks = 0; ks < 4; ks++) {
                uint32_t a0 = abase + rg * (16u * 144u) + ks * 32u;
                asm volatile("ldmatrix.sync.aligned.m8n8.x4.shared.b16 {%0,%1,%2,%3},[%4];"
                    : "=r"(ah[rg][ks][0]), "=r"(ah[rg][ks][1]),
                      "=r"(ah[rg][ks][2]), "=r"(ah[rg][ks][3]) : "r"(a0));
                uint32_t a1 = a0 + (AL_OFF - AH_OFF);
                asm volatile("ldmatrix.sync.aligned.m8n8.x4.shared.b16 {%0,%1,%2,%3},[%4];"
                    : "=r"(al[rg][ks][0]), "=r"(al[rg][ks][1]),
                      "=r"(al[rg][ks][2]), "=r"(al[rg][ks][3]) : "r"(a1));
            }
        }
    }

    // per-lane row & coords (lane = row within warp tile)
    int myn = base_n + warpRow + lane;
    bool pv = (myn < NPTS);
    int4 cc = coords[pv ? myn : 0];

    uint32_t bl_lane = (unsigned)(lane & 7) * 144u + ((unsigned)(lane >> 3) & 1u) * 16u;
    char* ebuf = smem + EPI_OFF + wid * 2048;

#pragma unroll 1
    for (int k = 0; k < 27; k++) {
        // rank for this lane's row at offset k
        unsigned rank = 0xFFFFFFFFu;
        {
            int ox = cc.y - k / 9;
            int oy = cc.z - (k / 3) % 3;
            int oz = cc.w - k % 3;
            if (pv && (unsigned)ox < SXD && (unsigned)oy < SYD && (unsigned)oz < SZD) {
                unsigned lin = (unsigned)ox * YZ + (unsigned)oy * SZD + (unsigned)oz;
                unsigned word = lin >> 5;
                rank = __ldg(&g_pref[word]) +
                       __popc(__ldg(&g_bitmap[word]) & ((1u << (lin & 31)) - 1u));
            }
        }

        float c[2][2][4];
#pragma unroll
        for (int rg = 0; rg < 2; rg++)
#pragma unroll
            for (int n2 = 0; n2 < 2; n2++)
#pragma unroll
                for (int q = 0; q < 4; q++) c[rg][n2][q] = 0.f;

        uint32_t bk = (unsigned)(k * 16) * 144u + bl_lane;
#pragma unroll
        for (int pass = 0; pass < 3; pass++) {
            uint32_t boff = sb + ((pass == 1) ? BL_OFF : BH_OFF) + bk;
#pragma unroll
            for (int kk = 0; kk < 4; kk++) {
#pragma unroll
                for (int n2 = 0; n2 < 2; n2++) {
                    uint32_t b0, b1;
                    uint32_t ba = boff + (unsigned)(n2 * 8) * 144u + (unsigned)kk * 32u;
                    asm volatile("ldmatrix.sync.aligned.m8n8.x2.shared.b16 {%0,%1},[%2];"
                                 : "=r"(b0), "=r"(b1) : "r"(ba));
                    if (pass == 2) {
                        MMA(c[0][n2], al[0][kk], b0, b1);
                        MMA(c[1][n2], al[1][kk], b0, b1);
                    } else {
                        MMA(c[0][n2], ah[0][kk], b0, b1);
                        MMA(c[1][n2], ah[1][kk], b0, b1);
                    }
                }
            }
        }

        // stage 32x16 tile to smem, then scatter as red.v4
        __syncwarp();
        {
            int r0 = (lane >> 2);
            int cb = (lane & 3) * 2;
#pragma unroll
            for (int rg = 0; rg < 2; rg++) {
#pragma unroll
                for (int n2 = 0; n2 < 2; n2++) {
                    int colb = n2 * 8 + cb;
                    *reinterpret_cast<float2*>(ebuf + (rg * 16 + r0) * 64 + colb * 4) =
                        make_float2(c[rg][n2][0], c[rg][n2][1]);
                    *reinterpret_cast<float2*>(ebuf + (rg * 16 + r0 + 8) * 64 + colb * 4) =
                        make_float2(c[rg][n2][2], c[rg][n2][3]);
                }
            }
        }
        __syncwarp();
#pragma unroll
        for (int j = 0; j < 4; j++) {
            int rw = j * 8 + (lane >> 2);
            int q = lane & 3;
            unsigned rr = __shfl_sync(0xffffffffu, rank, rw);
            if (rr != 0xFFFFFFFFu) {
                float4 v = *reinterpret_cast<const float4*>(ebuf + rw * 64 + q * 16);
                asm volatile("red.global.add.v4.f32 [%0], {%1,%2,%3,%4};"
                             :: "l"(out + (size_t)rr * 16 + q * 4),
                                "f"(v.x), "f"(v.y), "f"(v.z), "f"(v.w)
                             : "memory");
            }
        }
    }
}

// ---------------- launch ----------------
extern "C" void kernel_launch(void* const* d_in, const int* in_sizes, int n_in,
                              void* d_out, int out_size) {
    const float* feats = (const float*)d_in[0];
    const int*   coords = (const int*)d_in[1];
    const float* W = (const float*)d_in[2];
    const float* bias = (const float*)d_in[3];
    float* out = (float*)d_out;
    float* uniqf = out + (size_t)NKTOT * 16;

    cudaFuncSetAttribute(k_gemm, cudaFuncAttributeMaxDynamicSharedMemorySize, SMEM_SZ);

    k_zero<<<ZBLK + 27, 256>>>(W);
    k_mark<<<(NPTS + 255) / 256, 256>>>((const int4*)coords);
    k_scan1<<<NPART, 256>>>();
    k_scan2<<<1, 512>>>();
    k_combo<<<NPART + FOB, 256>>>((float4*)out, (const float4*)bias, uniqf);
    k_gemm<<<NCTA, 256, SMEM_SZ>>>((const float4*)feats, (const int4*)coords, out);
    k_emit<<<(WORDS + 255) / 256, 256>>>(uniqf);
}